// round 13
// baseline (speedup 1.0000x reference)
#include <cuda_runtime.h>

#define D 128
#define M_MEM 1000
#define L_MEM 64
#define L_X 64
#define C_N 100
#define L_C 32
#define L_Y 32
#define OUT_ROWS (1 + C_N)            /* 101 */
#define NSLOT 16
#define MAX_NORM 10.0f
#define RENORM_EPS 1e-7f
#define COS_EPS 1e-8f

// xs encoding (written by head kernel, read by all mem blocks via PDL).
__device__ float g_enc_x[D];
// slot accumulators: sum of exp(sim)*enc over mems, 16-way sliced by block id.
__device__ float g_acc[NSLOT][D];
__device__ float g_esum[NSLOT];
__device__ int   g_counter;          // zero-init; reset by finalizing block

// ---------------------------------------------------------------------------
// Encode body, L compile-time. 512 threads = 16 warps; warp w owns tokens
// w, w+16, ... Direct per-warp broadcast loads of ids/freqs; all row gathers
// in flight; interleaved norm reduces; uniform 1/||w|| applied at the end.
// Returns the encoding component for tid < D (0 otherwise); writes dst if
// non-null.
// ---------------------------------------------------------------------------
template <int L>
__device__ __forceinline__ float encode_body(
    const int* __restrict__ seq,
    const float* __restrict__ lt, const float* __restrict__ freqs,
    float* __restrict__ dst)
{
    constexpr int NW = 16;
    constexpr int NT = L / NW;

    __shared__ float sh_wsq[NW];
    __shared__ float sh_acc[NW][D];

    int tid  = threadIdx.x;
    int warp = tid >> 5;
    int lane = tid & 31;

    int idx[NT];
    #pragma unroll
    for (int k = 0; k < NT; k++)
        idx[k] = seq[warp + NW * k];

    float4 e[NT];
    #pragma unroll
    for (int k = 0; k < NT; k++)
        e[k] = __ldcs(reinterpret_cast<const float4*>(
                   lt + (size_t)idx[k] * D) + lane);

    float f[NT];
    #pragma unroll
    for (int k = 0; k < NT; k++)
        f[k] = freqs[idx[k]];

    {
        float ws = 0.0f;
        #pragma unroll
        for (int k = 0; k < NT; k++) ws += f[k] * f[k];
        if (lane == 0) sh_wsq[warp] = ws;
    }

    float sq[NT];
    #pragma unroll
    for (int k = 0; k < NT; k++)
        sq[k] = e[k].x * e[k].x + e[k].y * e[k].y
              + e[k].z * e[k].z + e[k].w * e[k].w;
    #pragma unroll
    for (int o = 16; o > 0; o >>= 1) {
        #pragma unroll
        for (int k = 0; k < NT; k++)
            sq[k] += __shfl_xor_sync(0xffffffffu, sq[k], o);
    }

    float4 acc = make_float4(0.0f, 0.0f, 0.0f, 0.0f);
    #pragma unroll
    for (int k = 0; k < NT; k++) {
        float n = sqrtf(sq[k]);
        float scale = (n > MAX_NORM) ? (MAX_NORM / (n + RENORM_EPS)) : 1.0f;
        float wl = f[k] * scale;
        acc.x += wl * e[k].x;
        acc.y += wl * e[k].y;
        acc.z += wl * e[k].z;
        acc.w += wl * e[k].w;
    }

    sh_acc[warp][lane * 4 + 0] = acc.x;
    sh_acc[warp][lane * 4 + 1] = acc.y;
    sh_acc[warp][lane * 4 + 2] = acc.z;
    sh_acc[warp][lane * 4 + 3] = acc.w;
    __syncthreads();

    float ret = 0.0f;
    if (tid < D) {
        float wsq = 0.0f;
        #pragma unroll
        for (int w = 0; w < NW; w++) wsq += sh_wsq[w];
        float s = 0.0f;
        #pragma unroll
        for (int w = 0; w < NW; w++) s += sh_acc[w][tid];
        ret = s * rsqrtf(wsq);
        if (dst) dst[tid] = ret;
    }
    return ret;
}

// ---------------------------------------------------------------------------
// Head kernel (1 block): zero accumulators, encode xs -> g_enc_x, trigger PDL.
// ---------------------------------------------------------------------------
__global__ __launch_bounds__(512) void head_kernel(
    const int* __restrict__ xs,
    const float* __restrict__ lt, const float* __restrict__ freqs)
{
    int tid = threadIdx.x;
    float* accf = &g_acc[0][0];
    for (int j = tid; j < NSLOT * D; j += 512) accf[j] = 0.0f;
    if (tid < NSLOT) g_esum[tid] = 0.0f;

    encode_body<L_X>(xs, lt, freqs, g_enc_x);

#if __CUDA_ARCH__ >= 900
    cudaTriggerProgrammaticLaunchCompletion();
#endif
}

// ---------------------------------------------------------------------------
// Main kernel (PDL after head): 1101 blocks.
//   b in 0..999    : encode mem b, fused sim+exp, atomic slot accumulate.
//   b == 1000      : encode ys  -> out row 101.
//   b in 1001..1100: encode cand -> out rows 102..201.
// Last mem block (counter) merges slots + xs self-term, writes xs_out rows.
// ---------------------------------------------------------------------------
__global__ __launch_bounds__(512) void main_kernel(
    const int* __restrict__ mems, const int* __restrict__ ys,
    const int* __restrict__ cands,
    const float* __restrict__ lt, const float* __restrict__ freqs,
    float* __restrict__ out)
{
    int b   = blockIdx.x;
    int tid = threadIdx.x;
    int warp = tid >> 5;
    int lane = tid & 31;

    if (b >= M_MEM) {
        if (b == M_MEM) {
            encode_body<L_Y>(ys, lt, freqs, out + (size_t)OUT_ROWS * D);
        } else {
            int c = b - M_MEM - 1;
            encode_body<L_C>(cands + (size_t)c * L_C, lt, freqs,
                             out + (size_t)(OUT_ROWS + 1 + c) * D);
        }
        return;
    }

    float s = encode_body<L_MEM>(mems + (size_t)b * L_MEM, lt, freqs, nullptr);

#if __CUDA_ARCH__ >= 900
    cudaGridDependencySynchronize();   // g_enc_x + zeroed accumulators ready
#endif

    __shared__ float red3[4][3];
    __shared__ float sh_ex, sh_xsq;

    float x = 0.0f;
    if (tid < D) {
        x = g_enc_x[tid];
        float pd = s * x, ps = s * s, px = x * x;
        #pragma unroll
        for (int o = 16; o > 0; o >>= 1) {
            pd += __shfl_xor_sync(0xffffffffu, pd, o);
            ps += __shfl_xor_sync(0xffffffffu, ps, o);
            px += __shfl_xor_sync(0xffffffffu, px, o);
        }
        if (lane == 0) {
            red3[warp][0] = pd;
            red3[warp][1] = ps;
            red3[warp][2] = px;
        }
    }
    __syncthreads();
    if (tid == 0) {
        float dot = red3[0][0] + red3[1][0] + red3[2][0] + red3[3][0];
        float ssq = red3[0][1] + red3[1][1] + red3[2][1] + red3[3][1];
        float xsq = red3[0][2] + red3[1][2] + red3[2][2] + red3[3][2];
        float nx = fmaxf(sqrtf(xsq), COS_EPS);
        float nm = fmaxf(sqrtf(ssq), COS_EPS);
        sh_ex  = expf(dot / (nx * nm));  // cosines in [-1,1]: no max shift
        sh_xsq = xsq;
    }
    __syncthreads();
    float ex = sh_ex;

    int slot = b & (NSLOT - 1);
    if (tid < D) atomicAdd(&g_acc[slot][tid], ex * s);
    if (tid == 0) atomicAdd(&g_esum[slot], ex);
    __threadfence();                    // every thread fences its own atomic
    __syncthreads();

    // --- last mem block finalizes ---
    __shared__ int sh_last;
    if (tid == 0) {
        int old = atomicAdd(&g_counter, 1);
        sh_last = (old == M_MEM - 1) ? 1 : 0;
    }
    __syncthreads();
    if (!sh_last) return;
    __threadfence();                    // acquire

    __shared__ float sh_tot;
    __shared__ float sh_exx;
    __shared__ float sh_lhs[D];

    if (tid == 0) {
        float tot = 0.0f;
        #pragma unroll
        for (int k = 0; k < NSLOT; k++) tot += __ldcg(&g_esum[k]);
        float xsq = sh_xsq;
        float nx = fmaxf(sqrtf(xsq), COS_EPS);
        float exx = expf(xsq / (nx * nx));   // xs self-sim term
        sh_exx = exx;
        sh_tot = tot + exx;
    }
    __syncthreads();

    if (tid < D) {
        float t = 0.0f;
        #pragma unroll
        for (int k = 0; k < NSLOT; k++) t += __ldcg(&g_acc[k][tid]);
        t += sh_exx * x;
        sh_lhs[tid] = t / sh_tot;
    }
    __syncthreads();

    for (int j = tid; j < OUT_ROWS * D; j += 512)
        out[j] = sh_lhs[j & (D - 1)];

    if (tid == 0) g_counter = 0;        // reset for next graph replay
}

extern "C" void kernel_launch(void* const* d_in, const int* in_sizes, int n_in,
                              void* d_out, int out_size) {
    const int*   xs    = (const int*)d_in[0];
    const int*   mems  = (const int*)d_in[1];
    const int*   ys    = (const int*)d_in[2];
    const int*   cands = (const int*)d_in[3];
    const float* lt    = (const float*)d_in[4];
    const float* freqs = (const float*)d_in[5];
    float* out = (float*)d_out;

    head_kernel<<<1, 512>>>(xs, lt, freqs);

    cudaLaunchConfig_t cfg = {};
    cfg.gridDim  = dim3(M_MEM + 1 + C_N, 1, 1);
    cfg.blockDim = dim3(512, 1, 1);
    cfg.dynamicSmemBytes = 0;
    cfg.stream = 0;
    cudaLaunchAttribute attrs[1];
    attrs[0].id = cudaLaunchAttributeProgrammaticStreamSerialization;
    attrs[0].val.programmaticStreamSerializationAllowed = 1;
    cfg.attrs = attrs;
    cfg.numAttrs = 1;
    cudaError_t err = cudaLaunchKernelEx(&cfg, main_kernel,
                                         mems, ys, cands, lt, freqs, out);
    if (err != cudaSuccess) {
        main_kernel<<<M_MEM + 1 + C_N, 512>>>(mems, ys, cands, lt, freqs, out);
    }
}

// round 14
// speedup vs baseline: 1.1215x; 1.1215x over previous
#include <cuda_runtime.h>

#define D 128
#define M_MEM 1000
#define L_MEM 64
#define L_X 64
#define C_N 100
#define L_C 32
#define L_Y 32
#define N_MEMS (M_MEM + 1)            /* 1001: row0=xs, rows1..1000=mems */
#define OUT_ROWS (1 + C_N)            /* 101 */
#define NBLK_B 32                     /* ceil(1001/32) */
#define N_EXTRA (1 + C_N)             /* ys + cands blocks, scheduled first */
#define MAX_NORM 10.0f
#define RENORM_EPS 1e-7f
#define COS_EPS 1e-8f

// row 0 = xs encoding, rows 1..1000 = mems encodings. 512.5 KB.
__device__ float g_enc[(size_t)N_MEMS * D];
// per-block partials from kernel B
__device__ float g_part[(size_t)NBLK_B * D];
__device__ float g_psum[NBLK_B];
__device__ int   g_counter;          // zero-init; reset by finalizing block

// ---------------------------------------------------------------------------
// Encode body, L compile-time. 512 threads = 16 warps; warp w owns tokens
// w, w+16, ... Direct per-warp broadcast id/freq loads; all row gathers in
// flight (default cache policy: the ~32MB unique-row working set can persist
// in L2 across graph replays); interleaved norm reduces; uniform 1/||w||
// applied once at the final write.
// ---------------------------------------------------------------------------
template <int L>
__device__ __forceinline__ void encode_body(
    const int* __restrict__ seq,
    const float* __restrict__ lt, const float* __restrict__ freqs,
    float* __restrict__ dst)
{
    constexpr int NW = 16;
    constexpr int NT = L / NW;

    __shared__ float sh_wsq[NW];
    __shared__ float sh_acc[NW][D];

    int tid  = threadIdx.x;
    int warp = tid >> 5;
    int lane = tid & 31;

    int idx[NT];
    #pragma unroll
    for (int k = 0; k < NT; k++)
        idx[k] = seq[warp + NW * k];

    float4 e[NT];
    #pragma unroll
    for (int k = 0; k < NT; k++)
        e[k] = *(reinterpret_cast<const float4*>(lt + (size_t)idx[k] * D) + lane);

    float f[NT];
    #pragma unroll
    for (int k = 0; k < NT; k++)
        f[k] = freqs[idx[k]];

    {
        float ws = 0.0f;
        #pragma unroll
        for (int k = 0; k < NT; k++) ws += f[k] * f[k];
        if (lane == 0) sh_wsq[warp] = ws;
    }

    float sq[NT];
    #pragma unroll
    for (int k = 0; k < NT; k++)
        sq[k] = e[k].x * e[k].x + e[k].y * e[k].y
              + e[k].z * e[k].z + e[k].w * e[k].w;
    #pragma unroll
    for (int o = 16; o > 0; o >>= 1) {
        #pragma unroll
        for (int k = 0; k < NT; k++)
            sq[k] += __shfl_xor_sync(0xffffffffu, sq[k], o);
    }

    float4 acc = make_float4(0.0f, 0.0f, 0.0f, 0.0f);
    #pragma unroll
    for (int k = 0; k < NT; k++) {
        float n = sqrtf(sq[k]);
        float scale = (n > MAX_NORM) ? (MAX_NORM / (n + RENORM_EPS)) : 1.0f;
        float wl = f[k] * scale;
        acc.x += wl * e[k].x;
        acc.y += wl * e[k].y;
        acc.z += wl * e[k].z;
        acc.w += wl * e[k].w;
    }

    sh_acc[warp][lane * 4 + 0] = acc.x;
    sh_acc[warp][lane * 4 + 1] = acc.y;
    sh_acc[warp][lane * 4 + 2] = acc.z;
    sh_acc[warp][lane * 4 + 3] = acc.w;
    __syncthreads();

    if (tid < D) {
        float wsq = 0.0f;
        #pragma unroll
        for (int w = 0; w < NW; w++) wsq += sh_wsq[w];
        float s = 0.0f;
        #pragma unroll
        for (int w = 0; w < NW; w++) s += sh_acc[w][tid];
        dst[tid] = s * rsqrtf(wsq);
    }
}

// ---------------------------------------------------------------------------
// Kernel A: encode all 1102 sequences (fully independent).
//   blocks 0..100   : ys + cands -> out rows (no B dependency)
//   block 101       : xs   -> g_enc row 0
//   blocks 102..1101: mems -> g_enc rows 1..1000
// Fires the PDL trigger after final stores so kernel B can roll out early.
// ---------------------------------------------------------------------------
__global__ __launch_bounds__(512) void encode_all(
    const int* __restrict__ xs, const int* __restrict__ mems,
    const int* __restrict__ ys, const int* __restrict__ cands,
    const float* __restrict__ lt, const float* __restrict__ freqs,
    float* __restrict__ out)
{
    int b = blockIdx.x;
    if (b == 0) {
        encode_body<L_Y>(ys, lt, freqs, out + (size_t)OUT_ROWS * D);
    } else if (b < N_EXTRA) {
        int c = b - 1;
        encode_body<L_C>(cands + (size_t)c * L_C, lt, freqs,
                         out + (size_t)(OUT_ROWS + 1 + c) * D);
    } else if (b == N_EXTRA) {
        encode_body<L_X>(xs, lt, freqs, g_enc);
    } else {
        int m = b - N_EXTRA - 1;
        encode_body<L_MEM>(mems + (size_t)m * L_MEM, lt, freqs,
                           g_enc + (size_t)(m + 1) * D);
    }
#if __CUDA_ARCH__ >= 900
    cudaTriggerProgrammaticLaunchCompletion();
#endif
}

// ---------------------------------------------------------------------------
// Kernel B: sims + exp + per-block partials; the LAST block (atomic counter)
// reduces the 32 partials in fixed order and writes the broadcast output.
// 32 blocks x 32 warps, one row per warp, PDL-launched.
// exp needs no max shift: cosines are in [-1,1].
// ---------------------------------------------------------------------------
__global__ __launch_bounds__(1024) void sims_finalize_kernel(float* __restrict__ out)
{
#if __CUDA_ARCH__ >= 900
    cudaGridDependencySynchronize();
#endif

    __shared__ float sh_part[32][D];
    __shared__ float sh_exp[32];

    int tid  = threadIdx.x;
    int warp = tid >> 5;
    int lane = tid & 31;
    int i = blockIdx.x * 32 + warp;
    bool valid = (i < N_MEMS);
    int r = valid ? ((i < M_MEM) ? (i + 1) : 0) : 0;

    float4 x = *reinterpret_cast<const float4*>(&g_enc[lane * 4]);
    float4 e = *reinterpret_cast<const float4*>(&g_enc[(size_t)r * D + lane * 4]);

    float dot = e.x * x.x + e.y * x.y + e.z * x.z + e.w * x.w;
    float esq = e.x * e.x + e.y * e.y + e.z * e.z + e.w * e.w;
    float xsq = x.x * x.x + x.y * x.y + x.z * x.z + x.w * x.w;
    #pragma unroll
    for (int o = 16; o > 0; o >>= 1) {
        dot += __shfl_xor_sync(0xffffffffu, dot, o);
        esq += __shfl_xor_sync(0xffffffffu, esq, o);
        xsq += __shfl_xor_sync(0xffffffffu, xsq, o);
    }
    float nx = fmaxf(sqrtf(xsq), COS_EPS);
    float nm = fmaxf(sqrtf(esq), COS_EPS);
    float ex = valid ? expf(dot / (nx * nm)) : 0.0f;

    sh_part[warp][lane * 4 + 0] = ex * e.x;
    sh_part[warp][lane * 4 + 1] = ex * e.y;
    sh_part[warp][lane * 4 + 2] = ex * e.z;
    sh_part[warp][lane * 4 + 3] = ex * e.w;
    if (lane == 0) sh_exp[warp] = ex;
    __syncthreads();

    if (tid < D) {
        float s = 0.0f;
        #pragma unroll
        for (int w = 0; w < 32; w++) s += sh_part[w][tid];
        g_part[(size_t)blockIdx.x * D + tid] = s;
    }
    if (tid == 0) {
        float s = 0.0f;
        #pragma unroll
        for (int w = 0; w < 32; w++) s += sh_exp[w];
        g_psum[blockIdx.x] = s;
    }
    __threadfence();
    __syncthreads();

    // --- last block finalizes ---
    __shared__ int sh_last;
    if (tid == 0) {
        int old = atomicAdd(&g_counter, 1);
        sh_last = (old == NBLK_B - 1) ? 1 : 0;
    }
    __syncthreads();
    if (!sh_last) return;
    __threadfence();

    __shared__ float cpart[8][D];
    __shared__ float sh_tot;
    __shared__ float sh_lhs[D];

    {
        int q = tid & 31;          // float4 column
        int chunk = tid >> 5;      // 0..31 -> use 0..7, 4 blocks each
        if (chunk < 8) {
            float4 acc = make_float4(0.0f, 0.0f, 0.0f, 0.0f);
            #pragma unroll
            for (int k = 0; k < 4; k++) {
                int bb = chunk * 4 + k;
                const float* p = &g_part[(size_t)bb * D + q * 4];
                acc.x += __ldcg(p + 0);
                acc.y += __ldcg(p + 1);
                acc.z += __ldcg(p + 2);
                acc.w += __ldcg(p + 3);
            }
            cpart[chunk][q * 4 + 0] = acc.x;
            cpart[chunk][q * 4 + 1] = acc.y;
            cpart[chunk][q * 4 + 2] = acc.z;
            cpart[chunk][q * 4 + 3] = acc.w;
        }
    }
    if (warp == 0) {
        float sm = (lane < NBLK_B) ? __ldcg(&g_psum[lane]) : 0.0f;
        #pragma unroll
        for (int o = 16; o > 0; o >>= 1)
            sm += __shfl_xor_sync(0xffffffffu, sm, o);
        if (lane == 0) sh_tot = sm;
    }
    __syncthreads();

    if (tid < D) {
        float s = 0.0f;
        #pragma unroll
        for (int c = 0; c < 8; c++) s += cpart[c][tid];
        sh_lhs[tid] = s / sh_tot;
    }
    __syncthreads();

    for (int j = tid; j < OUT_ROWS * D; j += 1024)
        out[j] = sh_lhs[j & (D - 1)];

    if (tid == 0) g_counter = 0;   // reset for next graph replay
}

extern "C" void kernel_launch(void* const* d_in, const int* in_sizes, int n_in,
                              void* d_out, int out_size) {
    const int*   xs    = (const int*)d_in[0];
    const int*   mems  = (const int*)d_in[1];
    const int*   ys    = (const int*)d_in[2];
    const int*   cands = (const int*)d_in[3];
    const float* lt    = (const float*)d_in[4];
    const float* freqs = (const float*)d_in[5];
    float* out = (float*)d_out;

    encode_all<<<2 + M_MEM + C_N, 512>>>(xs, mems, ys, cands, lt, freqs, out);

    // Kernel B with programmatic dependent launch: overlaps its CTA rollout
    // with A's tail; correctness guarded by cudaGridDependencySynchronize().
    cudaLaunchConfig_t cfg = {};
    cfg.gridDim  = dim3(NBLK_B, 1, 1);
    cfg.blockDim = dim3(1024, 1, 1);
    cfg.dynamicSmemBytes = 0;
    cfg.stream = 0;
    cudaLaunchAttribute attrs[1];
    attrs[0].id = cudaLaunchAttributeProgrammaticStreamSerialization;
    attrs[0].val.programmaticStreamSerializationAllowed = 1;
    cfg.attrs = attrs;
    cfg.numAttrs = 1;
    cudaError_t err = cudaLaunchKernelEx(&cfg, sims_finalize_kernel, out);
    if (err != cudaSuccess) {
        // Fallback: plain launch (still correct, just without overlap)
        sims_finalize_kernel<<<NBLK_B, 1024>>>(out);
    }
}

// round 17
// speedup vs baseline: 1.1538x; 1.0288x over previous
#include <cuda_runtime.h>

#define D 128
#define M_MEM 1000
#define L_MEM 64
#define L_X 64
#define C_N 100
#define L_C 32
#define L_Y 32
#define N_MEMS (M_MEM + 1)            /* 1001: row0=xs, rows1..1000=mems */
#define OUT_ROWS (1 + C_N)            /* 101 */
#define NBLK_B 32                     /* ceil(1001/32) */
#define MAX_NORM 10.0f
#define RENORM_EPS 1e-7f
#define COS_EPS 1e-8f

typedef unsigned long long u64;

// row 0 = xs encoding, rows 1..1000 = mems encodings. 512.5 KB.
__device__ float g_enc[(size_t)N_MEMS * D];
// per-block partials from kernel B
__device__ float g_part[(size_t)NBLK_B * D];
__device__ float g_psum[NBLK_B];
__device__ int   g_counter;          // zero-init; reset by finalizing block

// Table-row load with L2 evict-last cache-hint policy: the ~32MB unique-row
// working set fits in the 126MB L2, so pinning enables cross-replay retention.
__device__ __forceinline__ u64 make_evict_last_policy() {
    u64 pol;
    asm("createpolicy.fractional.L2::evict_last.b64 %0, 1.0;" : "=l"(pol));
    return pol;
}
__device__ __forceinline__ float4 ld_row_evict_last(const float* p, u64 pol) {
    float4 v;
    asm volatile("ld.global.L2::cache_hint.v4.f32 {%0, %1, %2, %3}, [%4], %5;"
                 : "=f"(v.x), "=f"(v.y), "=f"(v.z), "=f"(v.w)
                 : "l"(p), "l"(pol));
    return v;
}

// ---------------------------------------------------------------------------
// Encode body, L compile-time. 512 threads = 16 warps; warp w owns tokens
// w, w+16, ... Direct per-warp broadcast id/freq loads; all row gathers in
// flight; interleaved norm reduces; uniform 1/||w|| applied once at the end.
// ---------------------------------------------------------------------------
template <int L>
__device__ __forceinline__ void encode_body(
    const int* __restrict__ seq,
    const float* __restrict__ lt, const float* __restrict__ freqs,
    float* __restrict__ dst)
{
    constexpr int NW = 16;
    constexpr int NT = L / NW;

    __shared__ float sh_wsq[NW];
    __shared__ float sh_acc[NW][D];

    int tid  = threadIdx.x;
    int warp = tid >> 5;
    int lane = tid & 31;

    u64 pol = make_evict_last_policy();

    int idx[NT];
    #pragma unroll
    for (int k = 0; k < NT; k++)
        idx[k] = seq[warp + NW * k];

    float4 e[NT];
    #pragma unroll
    for (int k = 0; k < NT; k++)
        e[k] = ld_row_evict_last(lt + (size_t)idx[k] * D + lane * 4, pol);

    float f[NT];
    #pragma unroll
    for (int k = 0; k < NT; k++)
        f[k] = freqs[idx[k]];

    {
        float ws = 0.0f;
        #pragma unroll
        for (int k = 0; k < NT; k++) ws += f[k] * f[k];
        if (lane == 0) sh_wsq[warp] = ws;
    }

    float sq[NT];
    #pragma unroll
    for (int k = 0; k < NT; k++)
        sq[k] = e[k].x * e[k].x + e[k].y * e[k].y
              + e[k].z * e[k].z + e[k].w * e[k].w;
    #pragma unroll
    for (int o = 16; o > 0; o >>= 1) {
        #pragma unroll
        for (int k = 0; k < NT; k++)
            sq[k] += __shfl_xor_sync(0xffffffffu, sq[k], o);
    }

    float4 acc = make_float4(0.0f, 0.0f, 0.0f, 0.0f);
    #pragma unroll
    for (int k = 0; k < NT; k++) {
        float n = sqrtf(sq[k]);
        float scale = (n > MAX_NORM) ? (MAX_NORM / (n + RENORM_EPS)) : 1.0f;
        float wl = f[k] * scale;
        acc.x += wl * e[k].x;
        acc.y += wl * e[k].y;
        acc.z += wl * e[k].z;
        acc.w += wl * e[k].w;
    }

    sh_acc[warp][lane * 4 + 0] = acc.x;
    sh_acc[warp][lane * 4 + 1] = acc.y;
    sh_acc[warp][lane * 4 + 2] = acc.z;
    sh_acc[warp][lane * 4 + 3] = acc.w;
    __syncthreads();

    if (tid < D) {
        float wsq = 0.0f;
        #pragma unroll
        for (int w = 0; w < NW; w++) wsq += sh_wsq[w];
        float s = 0.0f;
        #pragma unroll
        for (int w = 0; w < NW; w++) s += sh_acc[w][tid];
        dst[tid] = s * rsqrtf(wsq);
    }
}

// ---------------------------------------------------------------------------
// Kernel A: encode all 1102 sequences (fully independent). Each block fires
// the PDL trigger after its final stores so kernel B can roll out early.
// ---------------------------------------------------------------------------
__global__ __launch_bounds__(512) void encode_all(
    const int* __restrict__ xs, const int* __restrict__ mems,
    const int* __restrict__ ys, const int* __restrict__ cands,
    const float* __restrict__ lt, const float* __restrict__ freqs,
    float* __restrict__ out)
{
    int b = blockIdx.x;
    if (b == 0) {
        encode_body<L_X>(xs, lt, freqs, g_enc);
    } else if (b <= M_MEM) {
        encode_body<L_MEM>(mems + (size_t)(b - 1) * L_MEM, lt, freqs,
                           g_enc + (size_t)b * D);
    } else if (b == M_MEM + 1) {
        encode_body<L_Y>(ys, lt, freqs, out + (size_t)OUT_ROWS * D);
    } else {
        int c = b - M_MEM - 2;
        encode_body<L_C>(cands + (size_t)c * L_C, lt, freqs,
                         out + (size_t)(OUT_ROWS + 1 + c) * D);
    }
#if __CUDA_ARCH__ >= 900
    cudaTriggerProgrammaticLaunchCompletion();
#endif
}

// ---------------------------------------------------------------------------
// Kernel B: sims + exp + per-block partials; the LAST block (atomic counter)
// reduces the 32 partials in fixed order and writes the broadcast output.
// 32 blocks x 32 warps, one row per warp, PDL-launched.
// exp needs no max shift: cosines are in [-1,1].
// ---------------------------------------------------------------------------
__global__ __launch_bounds__(1024) void sims_finalize_kernel(float* __restrict__ out)
{
#if __CUDA_ARCH__ >= 900
    cudaGridDependencySynchronize();
#endif

    __shared__ float sh_part[32][D];
    __shared__ float sh_exp[32];

    int tid  = threadIdx.x;
    int warp = tid >> 5;
    int lane = tid & 31;
    int i = blockIdx.x * 32 + warp;
    bool valid = (i < N_MEMS);
    int r = valid ? ((i < M_MEM) ? (i + 1) : 0) : 0;

    float4 x = *reinterpret_cast<const float4*>(&g_enc[lane * 4]);
    float4 e = *reinterpret_cast<const float4*>(&g_enc[(size_t)r * D + lane * 4]);

    float dot = e.x * x.x + e.y * x.y + e.z * x.z + e.w * x.w;
    float esq = e.x * e.x + e.y * e.y + e.z * e.z + e.w * e.w;
    float xsq = x.x * x.x + x.y * x.y + x.z * x.z + x.w * x.w;
    #pragma unroll
    for (int o = 16; o > 0; o >>= 1) {
        dot += __shfl_xor_sync(0xffffffffu, dot, o);
        esq += __shfl_xor_sync(0xffffffffu, esq, o);
        xsq += __shfl_xor_sync(0xffffffffu, xsq, o);
    }
    float nx = fmaxf(sqrtf(xsq), COS_EPS);
    float nm = fmaxf(sqrtf(esq), COS_EPS);
    float ex = valid ? expf(dot / (nx * nm)) : 0.0f;

    sh_part[warp][lane * 4 + 0] = ex * e.x;
    sh_part[warp][lane * 4 + 1] = ex * e.y;
    sh_part[warp][lane * 4 + 2] = ex * e.z;
    sh_part[warp][lane * 4 + 3] = ex * e.w;
    if (lane == 0) sh_exp[warp] = ex;
    __syncthreads();

    if (tid < D) {
        float s = 0.0f;
        #pragma unroll
        for (int w = 0; w < 32; w++) s += sh_part[w][tid];
        g_part[(size_t)blockIdx.x * D + tid] = s;
    }
    if (tid == 0) {
        float s = 0.0f;
        #pragma unroll
        for (int w = 0; w < 32; w++) s += sh_exp[w];
        g_psum[blockIdx.x] = s;
    }
    __threadfence();
    __syncthreads();

    // --- last block finalizes ---
    __shared__ int sh_last;
    if (tid == 0) {
        int old = atomicAdd(&g_counter, 1);
        sh_last = (old == NBLK_B - 1) ? 1 : 0;
    }
    __syncthreads();
    if (!sh_last) return;
    __threadfence();

    __shared__ float cpart[8][D];
    __shared__ float sh_tot;
    __shared__ float sh_lhs[D];

    {
        int q = tid & 31;          // float4 column
        int chunk = tid >> 5;      // 0..31 -> use 0..7, 4 blocks each
        if (chunk < 8) {
            float4 acc = make_float4(0.0f, 0.0f, 0.0f, 0.0f);
            #pragma unroll
            for (int k = 0; k < 4; k++) {
                int bb = chunk * 4 + k;
                const float* p = &g_part[(size_t)bb * D + q * 4];
                acc.x += __ldcg(p + 0);
                acc.y += __ldcg(p + 1);
                acc.z += __ldcg(p + 2);
                acc.w += __ldcg(p + 3);
            }
            cpart[chunk][q * 4 + 0] = acc.x;
            cpart[chunk][q * 4 + 1] = acc.y;
            cpart[chunk][q * 4 + 2] = acc.z;
            cpart[chunk][q * 4 + 3] = acc.w;
        }
    }
    if (warp == 0) {
        float sm = (lane < NBLK_B) ? __ldcg(&g_psum[lane]) : 0.0f;
        #pragma unroll
        for (int o = 16; o > 0; o >>= 1)
            sm += __shfl_xor_sync(0xffffffffu, sm, o);
        if (lane == 0) sh_tot = sm;
    }
    __syncthreads();

    if (tid < D) {
        float s = 0.0f;
        #pragma unroll
        for (int c = 0; c < 8; c++) s += cpart[c][tid];
        sh_lhs[tid] = s / sh_tot;
    }
    __syncthreads();

    for (int j = tid; j < OUT_ROWS * D; j += 1024)
        out[j] = sh_lhs[j & (D - 1)];

    if (tid == 0) g_counter = 0;   // reset for next graph replay
}

extern "C" void kernel_launch(void* const* d_in, const int* in_sizes, int n_in,
                              void* d_out, int out_size) {
    const int*   xs    = (const int*)d_in[0];
    const int*   mems  = (const int*)d_in[1];
    const int*   ys    = (const int*)d_in[2];
    const int*   cands = (const int*)d_in[3];
    const float* lt    = (const float*)d_in[4];
    const float* freqs = (const float*)d_in[5];
    float* out = (float*)d_out;

    encode_all<<<2 + M_MEM + C_N, 512>>>(xs, mems, ys, cands, lt, freqs, out);

    // Kernel B with programmatic dependent launch: overlaps its CTA rollout
    // with A's tail; correctness guarded by cudaGridDependencySynchronize().
    cudaLaunchConfig_t cfg = {};
    cfg.gridDim  = dim3(NBLK_B, 1, 1);
    cfg.blockDim = dim3(1024, 1, 1);
    cfg.dynamicSmemBytes = 0;
    cfg.stream = 0;
    cudaLaunchAttribute attrs[1];
    attrs[0].id = cudaLaunchAttributeProgrammaticStreamSerialization;
    attrs[0].val.programmaticStreamSerializationAllowed = 1;
    cfg.attrs = attrs;
    cfg.numAttrs = 1;
    cudaError_t err = cudaLaunchKernelEx(&cfg, sims_finalize_kernel, out);
    if (err != cudaSuccess) {
        // Fallback: plain launch (still correct, just without overlap)
        sims_finalize_kernel<<<NBLK_B, 1024>>>(out);
    }
}